// round 5
// baseline (speedup 1.0000x reference)
#include <cuda_runtime.h>

// Soft VQ encoding, fused fp32, packed-f32x2 (FFMA2) GEMM phases.
//   D = S[k]*(||x||^2 + ||c_k||^2 - 2 x.c_k);  A = softmax_k(D);
//   E[b,k,:] = sum_n A[b,n,k]*(X[b,n,:] - C[k,:])
// Shapes: X (8,16384,128) f32, C (128,128) f32, S (128,) f32 -> E (8,128,128) f32.

#define B_   8
#define N_   16384
#define D_   128
#define K_   128
#define CH   128          // rows per chunk
#define PAD  132          // padded row length in floats (132*4=528 B, 16B-aligned rows)
#define CPB  19           // CTAs per batch
#define GRID (B_ * CPB)   // 152
#define NT   256
#define CHUNKS_PER_B (N_ / CH)   // 128

#define SMEM_FLOATS (3 * K_ * PAD + 4 * K_)
#define SMEM_BYTES  (SMEM_FLOATS * 4)

typedef unsigned long long u64;

// packed f32x2 FMA: d = a*b + c elementwise on two packed floats
__device__ __forceinline__ u64 ffma2(u64 a, u64 b, u64 c) {
    u64 d;
    asm("fma.rn.f32x2 %0, %1, %2, %3;" : "=l"(d) : "l"(a), "l"(b), "l"(c));
    return d;
}
__device__ __forceinline__ u64 pk2(float lo, float hi) {
    u64 d;
    asm("mov.b64 %0, {%1, %2};" : "=l"(d) : "f"(lo), "f"(hi));
    return d;
}
__device__ __forceinline__ void upk2(float& lo, float& hi, u64 v) {
    asm("mov.b64 {%0, %1}, %2;" : "=f"(lo), "=f"(hi) : "l"(v));
}

// Exclusive per-CTA partial results (deterministic, no atomics). ~10 MB.
__device__ float g_partial[(size_t)GRID * K_ * D_];

__global__ __launch_bounds__(NT, 1)
void vq_fused_kernel(const float* __restrict__ X,
                     const float* __restrict__ C,
                     const float* __restrict__ S)
{
    extern __shared__ float smem[];
    float* Cs  = smem;                    // [K_][PAD]
    float* Xs  = Cs + K_ * PAD;           // [CH][PAD]
    float* As  = Xs + CH * PAD;           // [CH][PAD]  xc then A
    float* Sm2 = As + CH * PAD;           // -2*S        [K_]
    float* Ssc = Sm2 + K_;                // S*||c||^2   [K_]
    float* Ss  = Ssc + K_;                // S           [K_]
    float* COL = Ss + K_;                 // colsum      [K_]

    const int tid = threadIdx.x;
    const int kg  = tid >> 4;             // 0..15  (k group of 8)
    const int rg  = tid & 15;             // 0..15  (row group / d group)
    const int lane = tid & 31;
    const int wrp  = tid >> 5;
    const int kl   = lane * 4;            // softmax lane's 4 k columns

    // ---- load C into padded smem (coalesced) ----
    for (int i = tid; i < K_ * (D_ / 4); i += NT) {
        int k  = i >> 5;
        int d4 = i & 31;
        float4 v = reinterpret_cast<const float4*>(C)[i];
        *reinterpret_cast<float4*>(&Cs[k * PAD + d4 * 4]) = v;
    }
    __syncthreads();

    // ---- per-codeword constants ----
    if (tid < K_) {
        float c2 = 0.f;
        #pragma unroll
        for (int d4 = 0; d4 < 32; d4++) {
            float4 v = *reinterpret_cast<float4*>(&Cs[tid * PAD + d4 * 4]);
            c2 += v.x * v.x + v.y * v.y + v.z * v.z + v.w * v.w;
        }
        float s = S[tid];
        Ss[tid]  = s;
        Sm2[tid] = -2.f * s;
        Ssc[tid] = s * c2;
    }
    __syncthreads();

    // per-lane softmax constants
    float4 m2v = *reinterpret_cast<float4*>(&Sm2[kl]);
    float4 scv = *reinterpret_cast<float4*>(&Ssc[kl]);
    float4 ssv = *reinterpret_cast<float4*>(&Ss[kl]);

    // ---- chunk range for this CTA ----
    const int b   = blockIdx.x / CPB;
    const int t   = blockIdx.x % CPB;
    const int base = CHUNKS_PER_B / CPB;      // 6
    const int rem  = CHUNKS_PER_B % CPB;      // 14
    const int cnt  = base + (t < rem ? 1 : 0);
    const int st   = t * base + (t < rem ? t : rem);

    // persistent output accumulators (packed d-pairs) + colsum, live across chunks
    u64 eacc2[8][4];
    float cacc[8];
    #pragma unroll
    for (int i = 0; i < 8; i++) {
        cacc[i] = 0.f;
        #pragma unroll
        for (int j = 0; j < 4; j++) eacc2[i][j] = 0ull;
    }

    for (int ci = 0; ci < cnt; ci++) {
        const int chunk = st + ci;
        const float* Xg = X + ((size_t)b * N_ + (size_t)chunk * CH) * (size_t)D_;

        // ---- load X chunk ----
        for (int i = tid; i < CH * (D_ / 4); i += NT) {
            int r  = i >> 5;
            int d4 = i & 31;
            float4 v = reinterpret_cast<const float4*>(Xg)[i];
            *reinterpret_cast<float4*>(&Xs[r * PAD + d4 * 4]) = v;
        }
        __syncthreads();

        // ---- phase 1: XC = X . C^T  (8 rows x 8 k per thread, two j-halves,
        //      f32x2 packed along d; even/odd-d partial sums folded at end) ----
        #pragma unroll
        for (int jh = 0; jh < 2; jh++) {
            u64 acc2[8][4];
            #pragma unroll
            for (int i = 0; i < 8; i++)
                #pragma unroll
                for (int j = 0; j < 4; j++) acc2[i][j] = 0ull;

            #pragma unroll 1
            for (int d4 = 0; d4 < 32; d4++) {
                ulonglong2 xv[8];
                #pragma unroll
                for (int i = 0; i < 8; i++)
                    xv[i] = *reinterpret_cast<const ulonglong2*>(
                        &Xs[(rg + 16 * i) * PAD + d4 * 4]);
                #pragma unroll
                for (int j = 0; j < 4; j++) {
                    ulonglong2 cv = *reinterpret_cast<const ulonglong2*>(
                        &Cs[(kg * 8 + jh * 4 + j) * PAD + d4 * 4]);
                    #pragma unroll
                    for (int i = 0; i < 8; i++) {
                        acc2[i][j] = ffma2(xv[i].x, cv.x, acc2[i][j]);
                        acc2[i][j] = ffma2(xv[i].y, cv.y, acc2[i][j]);
                    }
                }
            }
            // fold packed partials and store 4 consecutive k as float4
            #pragma unroll
            for (int i = 0; i < 8; i++) {
                float r0l, r0h, r1l, r1h, r2l, r2h, r3l, r3h;
                upk2(r0l, r0h, acc2[i][0]);
                upk2(r1l, r1h, acc2[i][1]);
                upk2(r2l, r2h, acc2[i][2]);
                upk2(r3l, r3h, acc2[i][3]);
                *reinterpret_cast<float4*>(&As[(rg + 16 * i) * PAD + kg * 8 + jh * 4]) =
                    make_float4(r0l + r0h, r1l + r1h, r2l + r2h, r3l + r3h);
            }
        }
        __syncthreads();

        // ---- phase 2: per-row softmax of D = m2*xc + (S*X2 + S*C2) ----
        #pragma unroll 1
        for (int rr = 0; rr < 16; rr++) {
            int r = wrp * 16 + rr;
            float4 xv = *reinterpret_cast<float4*>(&Xs[r * PAD + kl]);
            float x2 = xv.x * xv.x + xv.y * xv.y + xv.z * xv.z + xv.w * xv.w;
            #pragma unroll
            for (int o = 16; o > 0; o >>= 1) x2 += __shfl_xor_sync(0xffffffffu, x2, o);

            float4 xc = *reinterpret_cast<float4*>(&As[r * PAD + kl]);
            float d0 = fmaf(m2v.x, xc.x, fmaf(ssv.x, x2, scv.x));
            float d1 = fmaf(m2v.y, xc.y, fmaf(ssv.y, x2, scv.y));
            float d2 = fmaf(m2v.z, xc.z, fmaf(ssv.z, x2, scv.z));
            float d3 = fmaf(m2v.w, xc.w, fmaf(ssv.w, x2, scv.w));

            float mx = fmaxf(fmaxf(d0, d1), fmaxf(d2, d3));
            #pragma unroll
            for (int o = 16; o > 0; o >>= 1) mx = fmaxf(mx, __shfl_xor_sync(0xffffffffu, mx, o));

            float e0 = __expf(d0 - mx);
            float e1 = __expf(d1 - mx);
            float e2 = __expf(d2 - mx);
            float e3 = __expf(d3 - mx);
            float sm = e0 + e1 + e2 + e3;
            #pragma unroll
            for (int o = 16; o > 0; o >>= 1) sm += __shfl_xor_sync(0xffffffffu, sm, o);
            float inv = 1.f / sm;
            *reinterpret_cast<float4*>(&As[r * PAD + kl]) =
                make_float4(e0 * inv, e1 * inv, e2 * inv, e3 * inv);
        }
        __syncthreads();

        // ---- phase 3: E += A^T . X  (8 k x 8 d per thread, f32x2 packed along d;
        //      accumulators persist across chunks in registers) ----
        #pragma unroll 1
        for (int n = 0; n < CH; n++) {
            float4 a0 = *reinterpret_cast<float4*>(&As[n * PAD + kg * 8]);
            float4 a1 = *reinterpret_cast<float4*>(&As[n * PAD + kg * 8 + 4]);
            ulonglong2 x0 = *reinterpret_cast<ulonglong2*>(&Xs[n * PAD + rg * 8]);
            ulonglong2 x1 = *reinterpret_cast<ulonglong2*>(&Xs[n * PAD + rg * 8 + 4]);
            u64 xp[4] = {x0.x, x0.y, x1.x, x1.y};
            float av[8] = {a0.x, a0.y, a0.z, a0.w, a1.x, a1.y, a1.z, a1.w};
            #pragma unroll
            for (int kk = 0; kk < 8; kk++) {
                u64 ap = pk2(av[kk], av[kk]);
                #pragma unroll
                for (int p = 0; p < 4; p++)
                    eacc2[kk][p] = ffma2(ap, xp[p], eacc2[kk][p]);
            }
            if (rg == 0) {
                #pragma unroll
                for (int kk = 0; kk < 8; kk++) cacc[kk] += av[kk];
            }
        }
        __syncthreads();   // As/Xs reused next chunk
    }

    // ---- final flush: P = E_partial - colsum * C ----
    if (rg == 0) {
        #pragma unroll
        for (int kk = 0; kk < 8; kk++) COL[kg * 8 + kk] = cacc[kk];
    }
    __syncthreads();

    float* P = g_partial + (size_t)blockIdx.x * (K_ * D_);
    #pragma unroll
    for (int kk = 0; kk < 8; kk++) {
        int k = kg * 8 + kk;
        float cs = COL[k];
        float e[8];
        #pragma unroll
        for (int p = 0; p < 4; p++) upk2(e[2 * p], e[2 * p + 1], eacc2[kk][p]);
        #pragma unroll
        for (int q = 0; q < 2; q++) {
            int d = rg * 8 + q * 4;
            float4 cv = *reinterpret_cast<float4*>(&Cs[k * PAD + d]);
            float4 o;
            o.x = e[q * 4 + 0] - cs * cv.x;
            o.y = e[q * 4 + 1] - cs * cv.y;
            o.z = e[q * 4 + 2] - cs * cv.z;
            o.w = e[q * 4 + 3] - cs * cv.w;
            *reinterpret_cast<float4*>(&P[k * D_ + d]) = o;
        }
    }
}

__global__ void vq_reduce_kernel(float* __restrict__ out)
{
    int i = blockIdx.x * blockDim.x + threadIdx.x;   // float4 index
    if (i >= (B_ * K_ * D_) / 4) return;
    int b = i >> 12;                  // / (K_*D_/4)
    int j = i & (K_ * D_ / 4 - 1);
    float4 s = make_float4(0.f, 0.f, 0.f, 0.f);
    #pragma unroll
    for (int t = 0; t < CPB; t++) {
        float4 v = reinterpret_cast<const float4*>(
            g_partial + ((size_t)(b * CPB + t)) * (K_ * D_))[j];
        s.x += v.x; s.y += v.y; s.z += v.z; s.w += v.w;
    }
    reinterpret_cast<float4*>(out)[i] = s;
}

extern "C" void kernel_launch(void* const* d_in, const int* in_sizes, int n_in,
                              void* d_out, int out_size)
{
    const float* X = nullptr;
    const float* C = nullptr;
    const float* S = nullptr;
    for (int i = 0; i < n_in; i++) {
        if (in_sizes[i] == B_ * N_ * D_)      X = (const float*)d_in[i];
        else if (in_sizes[i] == K_ * D_)      C = (const float*)d_in[i];
        else if (in_sizes[i] == K_)           S = (const float*)d_in[i];
    }
    float* out = (float*)d_out;

    cudaFuncSetAttribute(vq_fused_kernel,
                         cudaFuncAttributeMaxDynamicSharedMemorySize, SMEM_BYTES);
    vq_fused_kernel<<<GRID, NT, SMEM_BYTES>>>(X, C, S);
    vq_reduce_kernel<<<(B_ * K_ * D_ / 4 + 255) / 256, 256>>>(out);
}

// round 7
// speedup vs baseline: 2.0982x; 2.0982x over previous
#include <cuda_runtime.h>
#include <cuda_bf16.h>

typedef unsigned int u32; typedef unsigned short u16;

#define B_ 8
#define N_ 16384
#define D_ 128
#define K_ 128
#define CH 128
#define CPB 19
#define GRID (B_*CPB)
#define NT 256
#define CHUNKS_PER_B 128

#define RS 272                 /* tile row stride bytes = 68 u32 = 136 u16 */
#define TNM 34816              /* 128-row tile bytes */
#define TT  36992              /* 136-row tile bytes (XT, incl. ones row) */
#define OFF_X2  0
#define OFF_SM2 512
#define OFF_SSC 1024
#define OFF_SS  1536
#define OFF_CHI 2048
#define OFF_CLO (OFF_CHI+TNM)
#define OFF_XHI (OFF_CLO+TNM)      /* aliased as AT-hi after softmax */
#define OFF_XLO (OFF_XHI+TNM)      /* aliased as AT-lo */
#define OFF_XTH (OFF_XLO+TNM)
#define OFF_XTL (OFF_XTH+TT)
#define SMEM_BYTES (OFF_XTL+TT)    /* 215296 */

__device__ float g_partial[(size_t)GRID*K_*D_];

static __device__ __forceinline__ u32 cvta_s(const void* p){
    u32 a; asm("{ .reg .u64 t; cvta.to.shared.u64 t, %1; cvt.u32.u64 %0, t; }":"=r"(a):"l"(p)); return a;
}
static __device__ __forceinline__ void ldm4(u32&r0,u32&r1,u32&r2,u32&r3,u32 a){
    asm volatile("ldmatrix.sync.aligned.m8n8.x4.shared.b16 {%0,%1,%2,%3}, [%4];"
        : "=r"(r0),"=r"(r1),"=r"(r2),"=r"(r3) : "r"(a));
}
static __device__ __forceinline__ void ldm2(u32&r0,u32&r1,u32 a){
    asm volatile("ldmatrix.sync.aligned.m8n8.x2.shared.b16 {%0,%1}, [%2];"
        : "=r"(r0),"=r"(r1) : "r"(a));
}
static __device__ __forceinline__ void mma_bf(float* c, u32 a0,u32 a1,u32 a2,u32 a3, u32 b0,u32 b1){
    asm volatile("mma.sync.aligned.m16n8k16.row.col.f32.bf16.bf16.f32 "
        "{%0,%1,%2,%3}, {%4,%5,%6,%7}, {%8,%9}, {%0,%1,%2,%3};"
        : "+f"(c[0]),"+f"(c[1]),"+f"(c[2]),"+f"(c[3])
        : "r"(a0),"r"(a1),"r"(a2),"r"(a3),"r"(b0),"r"(b1));
}
static __device__ __forceinline__ void splitbf(float x, u16& h, u16& l){
    __nv_bfloat16 bh = __float2bfloat16(x);
    float r = x - __bfloat162float(bh);
    h = __bfloat16_as_ushort(bh);
    l = __bfloat16_as_ushort(__float2bfloat16(r));
}
static __device__ __forceinline__ u32 pkh(u16 a, u16 b){ return (u32)a | ((u32)b<<16); }

__global__ __launch_bounds__(NT, 1)
void vq_mma_kernel(const float* __restrict__ X, const float* __restrict__ C,
                   const float* __restrict__ S)
{
    extern __shared__ char sm[];
    const u32 smb = cvta_s(sm);
    const int tid = threadIdx.x, w = tid>>5, l = tid&31;

    // XT rows 128..135: row128 hi = 1.0 (colsum column), everything else 0
    for (int i = tid; i < 8*68; i += NT){
        int r = i/68, c = i%68;
        ((u32*)(sm+OFF_XTH))[(128+r)*68 + c] = (r==0) ? 0x3F803F80u : 0u;
        ((u32*)(sm+OFF_XTL))[(128+r)*68 + c] = 0u;
    }

    // ---- C -> Chi/Clo (k-major, padded rows) + ||c||^2 ----
    {
        int k = tid>>1, h = tid&1;
        const float* cr = C + k*D_ + h*64;
        u32* dh = (u32*)(sm+OFF_CHI) + k*68 + h*32;
        u32* dl = (u32*)(sm+OFF_CLO) + k*68 + h*32;
        float c2 = 0.f;
        #pragma unroll
        for (int i = 0; i < 16; i++){
            float4 v = *(const float4*)(cr + 4*i);
            float xs[4] = {v.x,v.y,v.z,v.w};
            u16 hb[4], lb[4];
            #pragma unroll
            for (int e = 0; e < 4; e++){ c2 += xs[e]*xs[e]; splitbf(xs[e], hb[e], lb[e]); }
            dh[2*i]   = pkh(hb[0],hb[1]);  dh[2*i+1] = pkh(hb[2],hb[3]);
            dl[2*i]   = pkh(lb[0],lb[1]);  dl[2*i+1] = pkh(lb[2],lb[3]);
        }
        c2 += __shfl_xor_sync(0xffffffffu, c2, 1);
        if (h == 0) ((float*)(sm+OFF_X2))[k] = c2;   // c2 scratch
    }
    __syncthreads();
    if (tid < K_){
        float s = S[tid], c2 = ((float*)(sm+OFF_X2))[tid];
        ((float*)(sm+OFF_SM2))[tid] = -2.f*s;
        ((float*)(sm+OFF_SSC))[tid] = s*c2;
        ((float*)(sm+OFF_SS ))[tid] = s;
    }
    __syncthreads();

    const int bb = blockIdx.x / CPB, tt = blockIdx.x % CPB;
    const int base = CHUNKS_PER_B / CPB, rem = CHUNKS_PER_B % CPB;
    const int cnt = base + (tt < rem ? 1 : 0);
    const int st  = tt*base + (tt < rem ? tt : rem);

    // ldmatrix lane address bases (per-lane constants)
    const u32 aA  = smb + OFF_XHI + (u32)((16*w + (l&15))*RS + 16*(l>>4));
    const u32 aB1 = smb + OFF_CHI + (u32)(((l&7) + 8*(l>>4))*RS + 16*((l>>3)&1));
    const u32 aB3 = smb + OFF_XTH + (u32)(((l&7) + 8*(l>>4))*RS + 16*((l>>3)&1));

    float Eg[17][4];
    #pragma unroll
    for (int j = 0; j < 17; j++){ Eg[j][0]=Eg[j][1]=Eg[j][2]=Eg[j][3]=0.f; }

    for (int ci = 0; ci < cnt; ci++){
        __syncthreads();   // previous chunk's phase-3 reads done before overwrite

        // ---- convert X chunk -> Xhi/Xlo + XThi/XTlo + x2 ----
        {
            const float* Xg = X + ((size_t)bb*N_ + (size_t)(st+ci)*CH)*(size_t)D_;
            int n = tid>>1, h = tid&1;
            const float* xr = Xg + n*D_ + h*64;
            u32* dh = (u32*)(sm+OFF_XHI) + n*68 + h*32;
            u32* dl = (u32*)(sm+OFF_XLO) + n*68 + h*32;
            u16* th = (u16*)(sm+OFF_XTH) + n;
            u16* tl = (u16*)(sm+OFF_XTL) + n;
            float x2 = 0.f;
            #pragma unroll
            for (int i = 0; i < 16; i++){
                float4 v = *(const float4*)(xr + 4*i);
                float xs[4] = {v.x,v.y,v.z,v.w};
                u16 hb[4], lb[4];
                #pragma unroll
                for (int e = 0; e < 4; e++){ x2 += xs[e]*xs[e]; splitbf(xs[e], hb[e], lb[e]); }
                dh[2*i]   = pkh(hb[0],hb[1]);  dh[2*i+1] = pkh(hb[2],hb[3]);
                dl[2*i]   = pkh(lb[0],lb[1]);  dl[2*i+1] = pkh(lb[2],lb[3]);
                #pragma unroll
                for (int e = 0; e < 4; e++){
                    int d = 64*h + 4*i + e;
                    th[d*136] = hb[e];
                    tl[d*136] = lb[e];
                }
            }
            x2 += __shfl_xor_sync(0xffffffffu, x2, 1);
            if (h == 0) ((float*)(sm+OFF_X2))[n] = x2;
        }
        __syncthreads();

        // ---- phase 1: logits (16 n8-frags per warp) = XhiChi + XhiClo + XloChi ----
        float Dg[16][4];
        #pragma unroll
        for (int j = 0; j < 16; j++){ Dg[j][0]=Dg[j][1]=Dg[j][2]=Dg[j][3]=0.f; }

        #pragma unroll 1
        for (int s = 0; s < 8; s++){
            u32 so = 32u*s;
            u32 ah0,ah1,ah2,ah3, al0,al1,al2,al3;
            ldm4(ah0,ah1,ah2,ah3, aA + so);
            ldm4(al0,al1,al2,al3, aA + TNM + so);
            #pragma unroll
            for (int p = 0; p < 8; p++){
                u32 bo = aB1 + (u32)(p*16*RS) + so;
                u32 bh0,bh1,bh2,bh3, bl0,bl1,bl2,bl3;
                ldm4(bh0,bh1,bh2,bh3, bo);
                ldm4(bl0,bl1,bl2,bl3, bo + TNM);
                mma_bf(Dg[2*p],   ah0,ah1,ah2,ah3, bh0,bh1);
                mma_bf(Dg[2*p],   ah0,ah1,ah2,ah3, bl0,bl1);
                mma_bf(Dg[2*p],   al0,al1,al2,al3, bh0,bh1);
                mma_bf(Dg[2*p+1], ah0,ah1,ah2,ah3, bh2,bh3);
                mma_bf(Dg[2*p+1], ah0,ah1,ah2,ah3, bl2,bl3);
                mma_bf(Dg[2*p+1], al0,al1,al2,al3, bh2,bh3);
            }
        }

        // ---- softmax in registers (rows n0 = 16w+gid, n1 = n0+8) ----
        {
            float x2a = ((float*)(sm+OFF_X2))[16*w + (l>>2)];
            float x2b = ((float*)(sm+OFF_X2))[16*w + (l>>2) + 8];
            #pragma unroll
            for (int j = 0; j < 16; j++){
                int c0 = 8*j + 2*(l&3);
                float2 m2 = *(const float2*)(sm + OFF_SM2 + c0*4);
                float2 sc = *(const float2*)(sm + OFF_SSC + c0*4);
                float2 sv = *(const float2*)(sm + OFF_SS  + c0*4);
                Dg[j][0] = fmaf(m2.x, Dg[j][0], fmaf(sv.x, x2a, sc.x));
                Dg[j][1] = fmaf(m2.y, Dg[j][1], fmaf(sv.y, x2a, sc.y));
                Dg[j][2] = fmaf(m2.x, Dg[j][2], fmaf(sv.x, x2b, sc.x));
                Dg[j][3] = fmaf(m2.y, Dg[j][3], fmaf(sv.y, x2b, sc.y));
            }
            float ma = -1e30f, mb = -1e30f;
            #pragma unroll
            for (int j = 0; j < 16; j++){
                ma = fmaxf(ma, fmaxf(Dg[j][0], Dg[j][1]));
                mb = fmaxf(mb, fmaxf(Dg[j][2], Dg[j][3]));
            }
            ma = fmaxf(ma, __shfl_xor_sync(0xffffffffu, ma, 1));
            ma = fmaxf(ma, __shfl_xor_sync(0xffffffffu, ma, 2));
            mb = fmaxf(mb, __shfl_xor_sync(0xffffffffu, mb, 1));
            mb = fmaxf(mb, __shfl_xor_sync(0xffffffffu, mb, 2));
            float sa = 0.f, sb = 0.f;
            #pragma unroll
            for (int j = 0; j < 16; j++){
                Dg[j][0] = __expf(Dg[j][0]-ma);  sa += Dg[j][0];
                Dg[j][1] = __expf(Dg[j][1]-ma);  sa += Dg[j][1];
                Dg[j][2] = __expf(Dg[j][2]-mb);  sb += Dg[j][2];
                Dg[j][3] = __expf(Dg[j][3]-mb);  sb += Dg[j][3];
            }
            sa += __shfl_xor_sync(0xffffffffu, sa, 1);
            sa += __shfl_xor_sync(0xffffffffu, sa, 2);
            sb += __shfl_xor_sync(0xffffffffu, sb, 1);
            sb += __shfl_xor_sync(0xffffffffu, sb, 2);
            float ia = 1.f/sa, ib = 1.f/sb;

            __syncthreads();   // everyone done reading Xhi/Xlo before AT overwrite

            int n0 = 16*w + (l>>2), n1 = n0 + 8;
            u16* ath = (u16*)(sm+OFF_XHI);
            u16* atl = (u16*)(sm+OFF_XLO);
            #pragma unroll
            for (int j = 0; j < 16; j++){
                int k0 = 8*j + 2*(l&3);
                u16 h0,l0, h1,l1, h2,l2, h3,l3;
                splitbf(Dg[j][0]*ia, h0, l0);
                splitbf(Dg[j][1]*ia, h1, l1);
                splitbf(Dg[j][2]*ib, h2, l2);
                splitbf(Dg[j][3]*ib, h3, l3);
                ath[k0*136 + n0]     = h0;  atl[k0*136 + n0]     = l0;
                ath[(k0+1)*136 + n0] = h1;  atl[(k0+1)*136 + n0] = l1;
                ath[k0*136 + n1]     = h2;  atl[k0*136 + n1]     = l2;
                ath[(k0+1)*136 + n1] = h3;  atl[(k0+1)*136 + n1] = l3;
            }
        }
        __syncthreads();

        // ---- phase 3: E[k][d] += AhiXhi + AloXhi + AhiXlo (+ ones col -> colsum) ----
        #pragma unroll 1
        for (int s = 0; s < 8; s++){
            u32 so = 32u*s;
            u32 ah0,ah1,ah2,ah3, al0,al1,al2,al3;
            ldm4(ah0,ah1,ah2,ah3, aA + so);          // AT-hi aliases XHI
            ldm4(al0,al1,al2,al3, aA + TNM + so);    // AT-lo aliases XLO
            #pragma unroll
            for (int p = 0; p < 8; p++){
                u32 bo = aB3 + (u32)(p*16*RS) + so;
                u32 bh0,bh1,bh2,bh3, bl0,bl1,bl2,bl3;
                ldm4(bh0,bh1,bh2,bh3, bo);
                ldm4(bl0,bl1,bl2,bl3, bo + TT);
                mma_bf(Eg[2*p],   ah0,ah1,ah2,ah3, bh0,bh1);
                mma_bf(Eg[2*p],   al0,al1,al2,al3, bh0,bh1);
                mma_bf(Eg[2*p],   ah0,ah1,ah2,ah3, bl0,bl1);
                mma_bf(Eg[2*p+1], ah0,ah1,ah2,ah3, bh2,bh3);
                mma_bf(Eg[2*p+1], al0,al1,al2,al3, bh2,bh3);
                mma_bf(Eg[2*p+1], ah0,ah1,ah2,ah3, bl2,bl3);
            }
            // frag 16: d-cols 128..135 (col 128 = ones -> colsum)
            u32 b0,b1, c0,c1;
            ldm2(b0,b1, aB3 + (u32)(128*RS) + so);
            ldm2(c0,c1, aB3 + TT + (u32)(128*RS) + so);
            mma_bf(Eg[16], ah0,ah1,ah2,ah3, b0,b1);
            mma_bf(Eg[16], al0,al1,al2,al3, b0,b1);
            mma_bf(Eg[16], ah0,ah1,ah2,ah3, c0,c1);
        }
    }

    // ---- epilogue: P[k][d] = E[k][d] - colsum[k]*C[k][d] ----
    {
        float cs0 = __shfl_sync(0xffffffffu, Eg[16][0], l & ~3);
        float cs1 = __shfl_sync(0xffffffffu, Eg[16][2], l & ~3);
        int k0 = 16*w + (l>>2), k1 = k0 + 8;
        float* P = g_partial + (size_t)blockIdx.x*(K_*D_);
        #pragma unroll
        for (int j = 0; j < 16; j++){
            int d0 = 8*j + 2*(l&3);
            float2 cv0 = *(const float2*)(C + k0*D_ + d0);
            float2 cv1 = *(const float2*)(C + k1*D_ + d0);
            float2 o0, o1;
            o0.x = Eg[j][0] - cs0*cv0.x;  o0.y = Eg[j][1] - cs0*cv0.y;
            o1.x = Eg[j][2] - cs1*cv1.x;  o1.y = Eg[j][3] - cs1*cv1.y;
            *(float2*)(P + k0*D_ + d0) = o0;
            *(float2*)(P + k1*D_ + d0) = o1;
        }
    }
}

__global__ void vq_reduce_kernel(float* __restrict__ out)
{
    int i = blockIdx.x * blockDim.x + threadIdx.x;
    if (i >= (B_*K_*D_)/4) return;
    int b = i >> 12, j = i & (K_*D_/4 - 1);
    float4 s = make_float4(0.f,0.f,0.f,0.f);
    #pragma unroll
    for (int t = 0; t < CPB; t++){
        float4 v = reinterpret_cast<const float4*>(g_partial + ((size_t)(b*CPB+t))*(K_*D_))[j];
        s.x += v.x; s.y += v.y; s.z += v.z; s.w += v.w;
    }
    reinterpret_cast<float4*>(out)[i] = s;
}

extern "C" void kernel_launch(void* const* d_in, const int* in_sizes, int n_in,
                              void* d_out, int out_size)
{
    const float *X = nullptr, *C = nullptr, *S = nullptr;
    for (int i = 0; i < n_in; i++){
        if      (in_sizes[i] == B_*N_*D_) X = (const float*)d_in[i];
        else if (in_sizes[i] == K_*D_)    C = (const float*)d_in[i];
        else if (in_sizes[i] == K_)       S = (const float*)d_in[i];
    }
    cudaFuncSetAttribute(vq_mma_kernel, cudaFuncAttributeMaxDynamicSharedMemorySize, SMEM_BYTES);
    vq_mma_kernel<<<GRID, NT, SMEM_BYTES>>>(X, C, S);
    vq_reduce_kernel<<<(B_*K_*D_/4 + 255)/256, 256>>>((float*)d_out);
}